// round 2
// baseline (speedup 1.0000x reference)
#include <cuda_runtime.h>
#include <stdint.h>

#define NN 100000
#define NE 1600000
#define NF 256
#define NH 64
#define NHTOT (NN * NH)          // 6,400,000

// Scratch (static device globals: no allocations allowed)
__device__ __align__(16) float g_support[NHTOT];   // x @ W
__device__ __align__(16) float g_agg[NHTOT];       // segment_sum + b
__device__ double g_sum[NH];
__device__ double g_sumsq[NH];
__device__ float g_scale[NH];
__device__ float g_shift[NH];

// ---------------------------------------------------------------------------
// init: agg = broadcast(b), zero BN accumulators
// ---------------------------------------------------------------------------
__global__ void k_init(const float* __restrict__ b) {
    int i = blockIdx.x * blockDim.x + threadIdx.x;
    if (i < NHTOT / 4) {
        float4 bv = reinterpret_cast<const float4*>(b)[i & 15];  // 16 float4s per 64-col row
        reinterpret_cast<float4*>(g_agg)[i] = bv;
    }
    if (blockIdx.x == 0 && threadIdx.x < NH) {
        g_sum[threadIdx.x] = 0.0;
        g_sumsq[threadIdx.x] = 0.0;
    }
}

// ---------------------------------------------------------------------------
// GEMM: support[NN,64] = x[NN,256] @ W[256,64]
// Block tile 128x64, 128 threads, 8x8 micro-tile, K-step 16.
// ---------------------------------------------------------------------------
__global__ __launch_bounds__(128) void k_gemm(const float* __restrict__ x,
                                              const float* __restrict__ W) {
    __shared__ float As[16][132];   // [k][row]
    __shared__ float Bs[16][64];    // [k][col]

    const int tid = threadIdx.x;
    const int tx = tid & 7;     // 0..7  -> output cols tx*8..tx*8+7
    const int ty = tid >> 3;    // 0..15 -> output rows ty*8..ty*8+7
    const int rowBase = blockIdx.x * 128;

    float acc[8][8];
#pragma unroll
    for (int i = 0; i < 8; i++)
#pragma unroll
        for (int j = 0; j < 8; j++) acc[i][j] = 0.0f;

    for (int k0 = 0; k0 < NF; k0 += 16) {
#pragma unroll
        for (int i = 0; i < 4; i++) {
            int idx = i * 512 + tid * 4;
            int r = idx >> 4;
            int kk = idx & 15;
            float4 v = make_float4(0.f, 0.f, 0.f, 0.f);
            int gr = rowBase + r;
            if (gr < NN)
                v = *reinterpret_cast<const float4*>(x + gr * NF + k0 + kk);
            As[kk + 0][r] = v.x;
            As[kk + 1][r] = v.y;
            As[kk + 2][r] = v.z;
            As[kk + 3][r] = v.w;
        }
#pragma unroll
        for (int i = 0; i < 2; i++) {
            int idx = i * 512 + tid * 4;
            int kk = idx >> 6;
            int c = idx & 63;
            *reinterpret_cast<float4*>(&Bs[kk][c]) =
                *reinterpret_cast<const float4*>(W + (k0 + kk) * NH + c);
        }
        __syncthreads();

#pragma unroll
        for (int kk = 0; kk < 16; kk++) {
            float a[8], bb[8];
            *reinterpret_cast<float4*>(&a[0]) = *reinterpret_cast<const float4*>(&As[kk][ty * 8]);
            *reinterpret_cast<float4*>(&a[4]) = *reinterpret_cast<const float4*>(&As[kk][ty * 8 + 4]);
            *reinterpret_cast<float4*>(&bb[0]) = *reinterpret_cast<const float4*>(&Bs[kk][tx * 8]);
            *reinterpret_cast<float4*>(&bb[4]) = *reinterpret_cast<const float4*>(&Bs[kk][tx * 8 + 4]);
#pragma unroll
            for (int i = 0; i < 8; i++)
#pragma unroll
                for (int j = 0; j < 8; j++) acc[i][j] = fmaf(a[i], bb[j], acc[i][j]);
        }
        __syncthreads();
    }

#pragma unroll
    for (int i = 0; i < 8; i++) {
        int gr = rowBase + ty * 8 + i;
        if (gr < NN) {
            float4 v0 = make_float4(acc[i][0], acc[i][1], acc[i][2], acc[i][3]);
            float4 v1 = make_float4(acc[i][4], acc[i][5], acc[i][6], acc[i][7]);
            *reinterpret_cast<float4*>(g_support + gr * NH + tx * 8) = v0;
            *reinterpret_cast<float4*>(g_support + gr * NH + tx * 8 + 4) = v1;
        }
    }
}

// ---------------------------------------------------------------------------
// Scatter: agg[row[e]] += ew[e] * support[col[e]]   (16 threads/edge, v4 red)
// ---------------------------------------------------------------------------
__global__ void k_scatter(const int* __restrict__ row, const int* __restrict__ col,
                          const float* __restrict__ ew) {
    int t = blockIdx.x * blockDim.x + threadIdx.x;
    int e = t >> 4;
    if (e >= NE) return;
    int l = t & 15;
    int c = __ldg(col + e);
    int r = __ldg(row + e);
    float w = __ldg(ew + e);
    float4 v = __ldg(reinterpret_cast<const float4*>(g_support) + c * 16 + l);
    float* dst = g_agg + r * 64 + l * 4;
    asm volatile("red.global.add.v4.f32 [%0], {%1, %2, %3, %4};"
                 :: "l"(dst), "f"(v.x * w), "f"(v.y * w), "f"(v.z * w), "f"(v.w * w)
                 : "memory");
}

// ---------------------------------------------------------------------------
// BN column stats
// ---------------------------------------------------------------------------
__global__ void k_colstats() {
    int j = threadIdx.x & 63;
    int grp = threadIdx.x >> 6;  // 0..3
    float s = 0.f, q = 0.f;
    for (int r = blockIdx.x * 4 + grp; r < NN; r += gridDim.x * 4) {
        float v = g_agg[r * 64 + j];
        s += v;
        q = fmaf(v, v, q);
    }
    __shared__ float ss[4][64], sq[4][64];
    ss[grp][j] = s;
    sq[grp][j] = q;
    __syncthreads();
    if (threadIdx.x < 64) {
        float S = ss[0][j] + ss[1][j] + ss[2][j] + ss[3][j];
        float Q = sq[0][j] + sq[1][j] + sq[2][j] + sq[3][j];
        atomicAdd(&g_sum[j], (double)S);
        atomicAdd(&g_sumsq[j], (double)Q);
    }
}

__global__ void k_finalize(const float* __restrict__ gamma, const float* __restrict__ beta) {
    int j = threadIdx.x;
    if (j < NH) {
        double mean = g_sum[j] / (double)NN;
        double var = g_sumsq[j] / (double)NN - mean * mean;
        float sc = (float)((double)gamma[j] * rsqrt(var + 1e-5));
        g_scale[j] = sc;
        g_shift[j] = beta[j] - (float)mean * sc;
    }
}

// ---------------------------------------------------------------------------
// Epilogue: BN affine + ReLU + JAX threefry dropout (PARTITIONABLE layout).
// Per element i: counter64 = i -> (hi=0, lo=i);
//   x0 = 0 + ks0, x1 = i + ks1; 20 rounds; bits = x0 ^ x1  (32-bit fold).
// key(42) -> (ks0, ks1) = (0, 42).
// ---------------------------------------------------------------------------
#define TF_R(r) { x0 += x1; x1 = __funnelshift_l(x1, x1, (r)); x1 ^= x0; }

__device__ __forceinline__ uint32_t tf_bits(uint32_t i) {
    const uint32_t ks0 = 0u, ks1 = 42u, ks2 = 0x1BD11BDAu ^ 42u;
    uint32_t x0 = ks0;        // counts_hi (=0) + ks0
    uint32_t x1 = i + ks1;    // counts_lo (=i) + ks1
    TF_R(13) TF_R(15) TF_R(26) TF_R(6)
    x0 += ks1; x1 += ks2 + 1u;
    TF_R(17) TF_R(29) TF_R(16) TF_R(24)
    x0 += ks2; x1 += ks0 + 2u;
    TF_R(13) TF_R(15) TF_R(26) TF_R(6)
    x0 += ks0; x1 += ks1 + 3u;
    TF_R(17) TF_R(29) TF_R(16) TF_R(24)
    x0 += ks1; x1 += ks2 + 4u;
    TF_R(13) TF_R(15) TF_R(26) TF_R(6)
    x0 += ks2; x1 += ks0 + 5u;
    return x0 ^ x1;
}

__global__ void k_out(float* __restrict__ out) {
    int base = (blockIdx.x * blockDim.x + threadIdx.x) * 4;
    if (base >= NHTOT) return;
    float4 v4 = *reinterpret_cast<const float4*>(g_agg + base);
    int j = base & 63;   // multiple of 4; j..j+3 within the 64-col row
    float vals[4] = {v4.x, v4.y, v4.z, v4.w};
    float res[4];
    const float inv_keep = 1.0f / 0.7f;
#pragma unroll
    for (int t = 0; t < 4; t++) {
        uint32_t bits = tf_bits((uint32_t)(base + t));
        float u = __uint_as_float((bits >> 9) | 0x3f800000u) - 1.0f;
        float v = fmaf(vals[t], g_scale[j + t], g_shift[j + t]);
        v = fmaxf(v, 0.0f);
        res[t] = (u < 0.7f) ? v * inv_keep : 0.0f;
    }
    *reinterpret_cast<float4*>(out + base) =
        make_float4(res[0], res[1], res[2], res[3]);
}

// ---------------------------------------------------------------------------
extern "C" void kernel_launch(void* const* d_in, const int* in_sizes, int n_in,
                              void* d_out, int out_size) {
    const float* x     = (const float*)d_in[0];
    const int*   row   = (const int*)d_in[1];
    const int*   col   = (const int*)d_in[2];
    const float* ew    = (const float*)d_in[3];
    const float* W     = (const float*)d_in[4];
    const float* b     = (const float*)d_in[5];
    const float* gamma = (const float*)d_in[6];
    const float* beta  = (const float*)d_in[7];
    float* out = (float*)d_out;

    k_init<<<(NHTOT / 4 + 255) / 256, 256>>>(b);
    k_gemm<<<(NN + 127) / 128, 128>>>(x, W);
    k_scatter<<<(NE * 16) / 256, 256>>>(row, col, ew);
    k_colstats<<<296, 256>>>();
    k_finalize<<<1, 64>>>(gamma, beta);
    k_out<<<(NHTOT / 4 + 255) / 256, 256>>>(out);
}